// round 3
// baseline (speedup 1.0000x reference)
#include <cuda_runtime.h>
#include <cuda_bf16.h>
#include <math.h>

// ---------------- problem constants ----------------
#define U_NN   50000
#define I_NN   25000
#define DD     64
#define DT     192        // D*(L+1)
#define RR     2
#define LL     2
#define E_UI   500000
#define E_TR   600000
#define E_II   400000
#define BB     512
#define KK     100
#define EPSV   1e-8f

// CSR graph layout: 5 graphs
//  g0: rel0  dst=user(50000) src=item   g1: rel1 same
//  g2: train dst=item(25000) src=user
//  g3: ig0   dst=item(25000) src=item   g4: ig1 same
#define NTOT   175000            // 50000*2 + 25000*3
#define ETOT   2400000           // 2*E_UI + E_TR + 2*E_II
#define DB0 0
#define DB1 50000
#define DB2 100000
#define DB3 125000
#define DB4 150000
#define EB0 0
#define EB1 (E_UI)
#define EB2 (2*E_UI)
#define EB3 (2*E_UI + E_TR)
#define EB4 (2*E_UI + E_TR + E_II)

// ---------------- scratch (static device globals) ----------------
__device__ __align__(16) float g_Uf[U_NN * DT];
__device__ __align__(16) float g_If[I_NN * DT];
__device__ __align__(16) float g_Sf[RR][I_NN * DT];
__device__ __align__(16) float g_Uagg[U_NN * DD];
__device__ __align__(16) float g_Iagg[I_NN * DD];
__device__ __align__(16) float g_IGagg[RR][I_NN * DD];
__device__            float g_cuser[U_NN * RR];
__device__            float g_invig[RR][I_NN];
__device__            float g_invdeg[I_NN];
__device__            int   g_cnt[NTOT];
__device__            int   g_off[NTOT];
__device__            int   g_cur[NTOT];
__device__            int   g_srcA[ETOT];
__device__ __align__(16) float g_aggsel[RR][BB * DT];
__device__ __align__(16) float g_G[RR][DT * DT];
__device__ __align__(16) float g_z[RR][BB * DT];

// ---------------- init ----------------
__global__ void k_zero_cnt() {
    int t = blockIdx.x * blockDim.x + threadIdx.x;
    if (t < NTOT) g_cnt[t] = 0;
}

__global__ void k_coeffs(const int* __restrict__ ubd, const int* __restrict__ igd,
                         const float* __restrict__ mgnn) {
    int t = blockIdx.x * blockDim.x + threadIdx.x;
    if (t < U_NN) {
        float m0 = mgnn[0], m1 = mgnn[1];
        float mx = fmaxf(m0, m1);
        float e0 = expf(m0 - mx), e1 = expf(m1 - mx);
        float inv = 1.0f / (e0 + e1);
        float w0 = e0 * inv, w1 = e1 * inv;
        float d0 = (float)ubd[t * 2 + 0], d1 = (float)ubd[t * 2 + 1];
        float itot = 1.0f / (d0 * w0 + d1 * w1 + EPSV);
        g_cuser[t * 2 + 0] = d0 * w0 * itot / (d0 + EPSV);
        g_cuser[t * 2 + 1] = d1 * w1 * itot / (d1 + EPSV);
    }
    if (t < I_NN) {
        g_invig[0][t] = 1.0f / ((float)igd[0 * I_NN + t] + EPSV);
        g_invig[1][t] = 1.0f / ((float)igd[1 * I_NN + t] + EPSV);
    }
}

__global__ void k_copy_emb(const float* __restrict__ ue, const float* __restrict__ ie) {
    int t = blockIdx.x * blockDim.x + threadIdx.x;
    int nU = U_NN * DD;
    if (t < nU) {
        int u = t >> 6, c = t & 63;
        g_Uf[u * DT + c] = ue[t];
    } else if (t < nU + I_NN * DD) {
        int j = t - nU;
        int i = j >> 6, c = j & 63;
        float v = ie[j];
        g_If[i * DT + c] = v;
        g_Sf[0][i * DT + c] = v;
        g_Sf[1][i * DT + c] = v;
    }
}

// ---------------- CSR build ----------------
__global__ void k_hist(const int* __restrict__ dst, int n, int cntBase) {
    int e = blockIdx.x * blockDim.x + threadIdx.x;
    if (e < n) atomicAdd(&g_cnt[cntBase + dst[e]], 1);
}

__global__ void k_scan() {
    __shared__ int sh[1024];
    const int DBv[5] = {DB0, DB1, DB2, DB3, DB4};
    const int DSv[5] = {U_NN, U_NN, I_NN, I_NN, I_NN};
    int g = blockIdx.x;
    int base = DBv[g], size = DSv[g];
    int t = threadIdx.x;
    int chunk = (size + 1023) >> 10;
    int lo = t * chunk;
    int hi = lo + chunk; if (hi > size) hi = size;
    if (lo > size) lo = size;
    int s = 0;
    for (int i = lo; i < hi; i++) s += g_cnt[base + i];
    sh[t] = s;
    __syncthreads();
    for (int off = 1; off < 1024; off <<= 1) {
        int v = (t >= off) ? sh[t - off] : 0;
        __syncthreads();
        sh[t] += v;
        __syncthreads();
    }
    int run = (t > 0) ? sh[t - 1] : 0;
    for (int i = lo; i < hi; i++) {
        g_off[base + i] = run;
        g_cur[base + i] = run;
        run += g_cnt[base + i];
    }
}

__global__ void k_invdeg() {
    int i = blockIdx.x * blockDim.x + threadIdx.x;
    if (i < I_NN) g_invdeg[i] = 1.0f / ((float)g_cnt[DB2 + i] + EPSV);
}

__global__ void k_place(const int* __restrict__ dst, const int* __restrict__ src,
                        int n, int cntBase, int edgeBase) {
    int e = blockIdx.x * blockDim.x + threadIdx.x;
    if (e < n) {
        int p = atomicAdd(&g_cur[cntBase + dst[e]], 1);
        g_srcA[edgeBase + p] = src[e];
    }
}

// ---------------- gather aggregation ----------------
// warp gathers + sums 64-float rows; lanes 0-15 handle even edges, 16-31 odd.
__device__ __forceinline__ float4 warp_gather_sum(const int* __restrict__ lst, int deg,
                                                  const float* __restrict__ feat,
                                                  int colOff, int lane, int half, int li) {
    float4 acc = make_float4(0.f, 0.f, 0.f, 0.f);
    for (int j0 = 0; j0 < deg; j0 += 32) {
        int m = deg - j0; if (m > 32) m = 32;
        int myidx = (j0 + lane < deg) ? __ldg(&lst[j0 + lane]) : 0;
        for (int k2 = 0; k2 < m; k2 += 2) {
            int kk = k2 + half;
            int idx = __shfl_sync(0xffffffffu, myidx, kk & 31);
            if (kk < m) {
                const float4 v = *reinterpret_cast<const float4*>(
                    feat + (long)idx * DT + colOff + li * 4);
                acc.x += v.x; acc.y += v.y; acc.z += v.z; acc.w += v.w;
            }
        }
    }
    return acc;
}

__device__ __forceinline__ float4 xhalf_reduce(float4 a) {
    a.x += __shfl_xor_sync(0xffffffffu, a.x, 16);
    a.y += __shfl_xor_sync(0xffffffffu, a.y, 16);
    a.z += __shfl_xor_sync(0xffffffffu, a.z, 16);
    a.w += __shfl_xor_sync(0xffffffffu, a.w, 16);
    return a;
}

__global__ void k_gather_users(int colOff) {
    int w = (blockIdx.x * blockDim.x + threadIdx.x) >> 5;
    if (w >= U_NN) return;
    int lane = threadIdx.x & 31, half = lane >> 4, li = lane & 15;
    int u = w;
    float4 a0 = warp_gather_sum(g_srcA + EB0 + g_off[DB0 + u], g_cnt[DB0 + u],
                                g_If, colOff, lane, half, li);
    float4 a1 = warp_gather_sum(g_srcA + EB1 + g_off[DB1 + u], g_cnt[DB1 + u],
                                g_If, colOff, lane, half, li);
    float c0 = g_cuser[u * 2 + 0], c1 = g_cuser[u * 2 + 1];
    float4 r;
    r.x = c0 * a0.x + c1 * a1.x;
    r.y = c0 * a0.y + c1 * a1.y;
    r.z = c0 * a0.z + c1 * a1.z;
    r.w = c0 * a0.w + c1 * a1.w;
    r = xhalf_reduce(r);
    if (half == 0)
        *reinterpret_cast<float4*>(&g_Uagg[(long)u * DD + li * 4]) = r;
}

__global__ void k_gather_items(int colOff) {
    int w = (blockIdx.x * blockDim.x + threadIdx.x) >> 5;
    if (w >= 3 * I_NN) return;
    int g = w / I_NN;
    int i = w - g * I_NN;
    int lane = threadIdx.x & 31, half = lane >> 4, li = lane & 15;
    float4 a; float c; float* dst;
    if (g == 0) {
        a = warp_gather_sum(g_srcA + EB2 + g_off[DB2 + i], g_cnt[DB2 + i],
                            g_Uf, colOff, lane, half, li);
        c = g_invdeg[i]; dst = g_Iagg;
    } else if (g == 1) {
        a = warp_gather_sum(g_srcA + EB3 + g_off[DB3 + i], g_cnt[DB3 + i],
                            g_If, colOff, lane, half, li);
        c = g_invig[0][i]; dst = g_IGagg[0];
    } else {
        a = warp_gather_sum(g_srcA + EB4 + g_off[DB4 + i], g_cnt[DB4 + i],
                            g_If, colOff, lane, half, li);
        c = g_invig[1][i]; dst = g_IGagg[1];
    }
    float4 r = make_float4(a.x * c, a.y * c, a.z * c, a.w * c);
    r = xhalf_reduce(r);
    if (half == 0)
        *reinterpret_cast<float4*>(&dst[(long)i * DD + li * 4]) = r;
}

// ---------------- dense projections ----------------
__device__ __forceinline__ const float* agg_ptr(int s) {
    switch (s) { case 0: return g_Uagg; case 1: return g_Iagg;
                 case 2: return g_IGagg[0]; default: return g_IGagg[1]; }
}
__device__ __forceinline__ float* feat_ptr_w(int s) {
    switch (s) { case 0: return g_Uf; case 1: return g_If;
                 case 2: return g_Sf[0]; default: return g_Sf[1]; }
}

__global__ void k_gemm64(int srcSel, const float* __restrict__ W,
                         int dstSel, int colOff, int N) {
    __shared__ __align__(16) float Ws[64 * 64];
    __shared__ __align__(16) float As[64 * 68];
    const float* src = agg_ptr(srcSel);
    float* dst = feat_ptr_w(dstSel);
    int tid = threadIdx.x;
    int row0 = blockIdx.x * 64;

    for (int i = tid; i < 4096; i += 256) Ws[i] = W[i];
    for (int i = tid; i < 4096; i += 256) {
        int rr = i >> 6, k = i & 63;
        float v = (row0 + rr < N) ? src[(long)(row0 + rr) * DD + k] : 0.f;
        As[k * 68 + rr] = v;
    }
    __syncthreads();

    int cg = tid & 15, rg = tid >> 4;
    float acc[4][4];
#pragma unroll
    for (int i = 0; i < 4; i++)
#pragma unroll
        for (int j = 0; j < 4; j++) acc[i][j] = 0.f;

#pragma unroll 8
    for (int k = 0; k < 64; k++) {
        float4 a4 = *reinterpret_cast<const float4*>(&As[k * 68 + rg * 4]);
        float4 w4 = *reinterpret_cast<const float4*>(&Ws[k * 64 + cg * 4]);
        float a[4] = {a4.x, a4.y, a4.z, a4.w};
        float w[4] = {w4.x, w4.y, w4.z, w4.w};
#pragma unroll
        for (int i = 0; i < 4; i++)
#pragma unroll
            for (int j = 0; j < 4; j++) acc[i][j] += a[i] * w[j];
    }
#pragma unroll
    for (int i = 0; i < 4; i++) {
        int row = row0 + rg * 4 + i;
        if (row < N) {
            float4 o = make_float4(acc[i][0], acc[i][1], acc[i][2], acc[i][3]);
            *reinterpret_cast<float4*>(&dst[(long)row * DT + colOff + cg * 4]) = o;
        }
    }
}

// ---------------- scoring ----------------
__global__ void k_G(const float* __restrict__ bW, float* out, int lossIdx) {
    __shared__ float Asm[32 * 192];
    __shared__ float Bsm[32 * 192];
    if (blockIdx.x == 0 && blockIdx.y == 0 && blockIdx.z == 0 && threadIdx.x == 0)
        out[lossIdx] = 0.f;
    int r = blockIdx.z;
    const float* W = bW + (long)r * DT * DT;
    int i0 = blockIdx.x * 32, j0 = blockIdx.y * 32;
    for (int t = threadIdx.x; t < 32 * 192; t += 256) {
        Asm[t] = W[(long)(i0 + t / 192) * DT + (t % 192)];
        Bsm[t] = W[(long)(j0 + t / 192) * DT + (t % 192)];
    }
    __syncthreads();
    int tj = threadIdx.x & 15, ti = threadIdx.x >> 4;
    float acc[2][2] = {{0.f, 0.f}, {0.f, 0.f}};
    for (int k = 0; k < 192; k++) {
        float a0 = Asm[(ti * 2 + 0) * 192 + k];
        float a1 = Asm[(ti * 2 + 1) * 192 + k];
        float b0 = Bsm[(tj * 2 + 0) * 192 + k];
        float b1 = Bsm[(tj * 2 + 1) * 192 + k];
        acc[0][0] += a0 * b0; acc[0][1] += a0 * b1;
        acc[1][0] += a1 * b0; acc[1][1] += a1 * b1;
    }
#pragma unroll
    for (int i = 0; i < 2; i++)
#pragma unroll
        for (int j = 0; j < 2; j++)
            g_G[r][(long)(i0 + ti * 2 + i) * DT + (j0 + tj * 2 + j)] = acc[i][j];
}

// score2 user-side agg through rel CSR lists of the batched users (warp per (b,r))
__global__ void k_aggsel(const int* __restrict__ users, const int* __restrict__ ubd) {
    int w = (blockIdx.x * blockDim.x + threadIdx.x) >> 5;
    if (w >= BB * RR) return;
    int b = w >> 1, r = w & 1;
    int lane = threadIdx.x & 31;
    int u = users[b];
    int cb = (r ? DB1 : DB0) + u;
    const int* lst = g_srcA + (r ? EB1 : EB0) + g_off[cb];
    int deg = g_cnt[cb];
    const float* S = g_Sf[r];
    float acc[6] = {0.f, 0.f, 0.f, 0.f, 0.f, 0.f};
    for (int j = 0; j < deg; j++) {
        int idx = __ldg(&lst[j]);
        const float* row = S + (long)idx * DT;
#pragma unroll
        for (int k = 0; k < 6; k++) acc[k] += row[lane + 32 * k];
    }
    float coeff = 1.0f / ((float)ubd[u * 2 + r] + EPSV);
    float* d = g_aggsel[r] + (long)b * DT;
#pragma unroll
    for (int k = 0; k < 6; k++) d[lane + 32 * k] = acc[k] * coeff;
}

__global__ void k_z() {
    __shared__ float a_s[DT];
    int b = blockIdx.x, r = blockIdx.y, c = threadIdx.x;
    a_s[c] = g_aggsel[r][(long)b * DT + c];
    __syncthreads();
    float acc = 0.f;
    for (int k = 0; k < DT; k++) acc += a_s[k] * g_G[r][(long)k * DT + c];
    g_z[r][(long)b * DT + c] = acc;
}

__global__ void k_bu_l2(const int* __restrict__ users, float* out, int lossIdx) {
    int w = (blockIdx.x * blockDim.x + threadIdx.x) >> 5;
    int lane = threadIdx.x & 31;
    if (w >= BB) return;
    int u = users[w];
    float s = 0.f;
    for (int c = lane; c < DT; c += 32) {
        float v = g_Uf[(long)u * DT + c];
        s += v * v;
    }
#pragma unroll
    for (int off = 16; off; off >>= 1) s += __shfl_down_sync(0xffffffffu, s, off);
    if (lane == 0) atomicAdd(out + lossIdx, 1e-4f * (float)KK * s);
}

__global__ void k_score(const int* __restrict__ users, const int* __restrict__ items,
                        float* out, int lossIdx) {
    __shared__ float l2blk;
    if (threadIdx.x == 0) l2blk = 0.f;
    __syncthreads();
    int w = (blockIdx.x * blockDim.x + threadIdx.x) >> 5;
    int lane = threadIdx.x & 31;
    if (w < BB * KK) {
        int b = w / KK;
        int u = users[b];
        int it = items[w];
        float s1 = 0.f, s2a = 0.f, s2b = 0.f, l2i = 0.f;
        for (int c = lane; c < DT; c += 32) {
            float bu = g_Uf[(long)u * DT + c];
            float bi = g_If[(long)it * DT + c];
            s1 += bu * bi;
            l2i += bi * bi;
            s2a += g_z[0][(long)b * DT + c] * g_Sf[0][(long)it * DT + c];
            s2b += g_z[1][(long)b * DT + c] * g_Sf[1][(long)it * DT + c];
        }
#pragma unroll
        for (int off = 16; off; off >>= 1) {
            s1  += __shfl_down_sync(0xffffffffu, s1, off);
            s2a += __shfl_down_sync(0xffffffffu, s2a, off);
            s2b += __shfl_down_sync(0xffffffffu, s2b, off);
            l2i += __shfl_down_sync(0xffffffffu, l2i, off);
        }
        if (lane == 0) {
            out[w] = 0.5f * s1 + 0.25f * (s2a + s2b);
            atomicAdd(&l2blk, l2i);
        }
    }
    __syncthreads();
    if (threadIdx.x == 0) atomicAdd(out + lossIdx, 1e-4f * l2blk);
}

// ---------------- launch ----------------
extern "C" void kernel_launch(void* const* d_in, const int* in_sizes, int n_in,
                              void* d_out, int out_size) {
    const float* ue    = (const float*)d_in[0];
    const float* ie    = (const float*)d_in[1];
    const float* W_ui  = (const float*)d_in[2];
    const float* W_ii  = (const float*)d_in[3];
    const float* bW    = (const float*)d_in[4];
    const float* mgnn  = (const float*)d_in[5];
    const int* rel_r   = (const int*)d_in[6];
    const int* rel_c   = (const int*)d_in[7];
    const int* tr_r    = (const int*)d_in[8];
    const int* tr_c    = (const int*)d_in[9];
    const int* ig_r    = (const int*)d_in[10];
    const int* ig_c    = (const int*)d_in[11];
    const int* ubd     = (const int*)d_in[12];
    const int* igd     = (const int*)d_in[13];
    const int* users   = (const int*)d_in[14];
    const int* items   = (const int*)d_in[15];
    float* out = (float*)d_out;
    int lossIdx = out_size - 1;

    const int T = 256;
    auto g = [](long n, int t) { return (int)((n + t - 1) / t); };

    // init + CSR build
    k_zero_cnt<<<g(NTOT, T), T>>>();
    k_coeffs<<<g(U_NN, T), T>>>(ubd, igd, mgnn);
    k_copy_emb<<<g((long)(U_NN + I_NN) * DD, T), T>>>(ue, ie);
    k_hist<<<g(E_UI, T), T>>>(rel_r, E_UI, DB0);
    k_hist<<<g(E_UI, T), T>>>(rel_r + E_UI, E_UI, DB1);
    k_hist<<<g(E_TR, T), T>>>(tr_c, E_TR, DB2);
    k_hist<<<g(E_II, T), T>>>(ig_r, E_II, DB3);
    k_hist<<<g(E_II, T), T>>>(ig_r + E_II, E_II, DB4);
    k_scan<<<5, 1024>>>();
    k_invdeg<<<g(I_NN, T), T>>>();
    k_place<<<g(E_UI, T), T>>>(rel_r, rel_c, E_UI, DB0, EB0);
    k_place<<<g(E_UI, T), T>>>(rel_r + E_UI, rel_c + E_UI, E_UI, DB1, EB1);
    k_place<<<g(E_TR, T), T>>>(tr_c, tr_r, E_TR, DB2, EB2);
    k_place<<<g(E_II, T), T>>>(ig_r, ig_c, E_II, DB3, EB3);
    k_place<<<g(E_II, T), T>>>(ig_r + E_II, ig_c + E_II, E_II, DB4, EB4);

    // propagation layers (CSR reused across layers)
    for (int l = 0; l < LL; l++) {
        int colOff = l * DD;
        k_gather_users<<<g((long)U_NN * 32, T), T>>>(colOff);
        k_gather_items<<<g((long)3 * I_NN * 32, T), T>>>(colOff);
        k_gemm64<<<g(U_NN, 64), 256>>>(0, W_ui + (long)l * DD * DD, 0, (l + 1) * DD, U_NN);
        k_gemm64<<<g(I_NN, 64), 256>>>(1, W_ui + (long)l * DD * DD, 1, (l + 1) * DD, I_NN);
        for (int r = 0; r < RR; r++)
            k_gemm64<<<g(I_NN, 64), 256>>>(2 + r, W_ii + (long)(r * LL + l) * DD * DD,
                                           2 + r, (l + 1) * DD, I_NN);
    }

    // scoring
    {
        dim3 gg(6, 6, 2);
        k_G<<<gg, 256>>>(bW, out, lossIdx);
    }
    k_aggsel<<<g((long)BB * RR * 32, T), T>>>(users, ubd);
    {
        dim3 gz(BB, RR);
        k_z<<<gz, DT>>>();
    }
    k_bu_l2<<<g((long)BB * 32, T), T>>>(users, out, lossIdx);
    k_score<<<g((long)BB * KK * 32, T), T>>>(users, items, out, lossIdx);
}

// round 4
// speedup vs baseline: 1.6280x; 1.6280x over previous
#include <cuda_runtime.h>
#include <cuda_bf16.h>
#include <math.h>

// ---------------- problem constants ----------------
#define U_NN   50000
#define I_NN   25000
#define DD     64
#define DT     192
#define RR     2
#define LL     2
#define E_UI   500000
#define E_TR   600000
#define E_II   400000
#define BB     512
#define KK     100
#define EPSV   1e-8f

// CSR: 5 graphs. g0/g1: rel r=0/1 (dst=user, src=item); g2: train (dst=item, src=user);
// g3/g4: ig r=0/1 (dst=item, src=item)
#define NTOT   175000
#define ETOT   2400000
#define DB0 0
#define DB1 50000
#define DB2 100000
#define DB3 125000
#define DB4 150000
#define EB1 (E_UI)
#define EB2 (2*E_UI)
#define EB3 (2*E_UI + E_TR)
#define EB4 (2*E_UI + E_TR + E_II)

// ---------------- device scratch ----------------
__device__ __align__(16) float g_Uf[U_NN * DT];
__device__ __align__(16) float g_If[I_NN * DT];
__device__ __align__(16) float g_Sf[RR][I_NN * DT];
__device__ __align__(16) float g_Uagg[U_NN * DD];
__device__ __align__(16) float g_Iagg[I_NN * DD];
__device__ __align__(16) float g_IGagg[RR][I_NN * DD];
__device__            float g_cuser[U_NN * RR];
__device__            float g_invig[RR][I_NN];
__device__            float g_invdeg[I_NN];
__device__            int   g_cnt[NTOT];
__device__            int   g_off[NTOT];
__device__            int   g_cur[NTOT];
__device__            int   g_srcA[ETOT];
__device__ __align__(16) float g_G[RR][DT * DT];
__device__ __align__(16) float g_z[RR][BB * DT];

// ---------------- init: zero cnt + coeffs + copy embeddings ----------------
__global__ void k_init(const float* __restrict__ ue, const float* __restrict__ ie,
                       const int* __restrict__ ubd, const int* __restrict__ igd,
                       const float* __restrict__ mgnn) {
    int t = blockIdx.x * blockDim.x + threadIdx.x;
    if (t < NTOT) g_cnt[t] = 0;
    if (t < U_NN) {
        float m0 = mgnn[0], m1 = mgnn[1];
        float mx = fmaxf(m0, m1);
        float e0 = expf(m0 - mx), e1 = expf(m1 - mx);
        float inv = 1.0f / (e0 + e1);
        float w0 = e0 * inv, w1 = e1 * inv;
        float d0 = (float)ubd[t * 2 + 0], d1 = (float)ubd[t * 2 + 1];
        float itot = 1.0f / (d0 * w0 + d1 * w1 + EPSV);
        g_cuser[t * 2 + 0] = d0 * w0 * itot / (d0 + EPSV);
        g_cuser[t * 2 + 1] = d1 * w1 * itot / (d1 + EPSV);
    }
    if (t < I_NN) {
        g_invig[0][t] = 1.0f / ((float)igd[0 * I_NN + t] + EPSV);
        g_invig[1][t] = 1.0f / ((float)igd[1 * I_NN + t] + EPSV);
    }
    int nU = U_NN * DD;
    if (t < nU) {
        int u = t >> 6, c = t & 63;
        g_Uf[u * DT + c] = ue[t];
    } else if (t < nU + I_NN * DD) {
        int j = t - nU;
        int i = j >> 6, c = j & 63;
        float v = ie[j];
        g_If[i * DT + c] = v;
        g_Sf[0][i * DT + c] = v;
        g_Sf[1][i * DT + c] = v;
    }
}

// ---------------- CSR build ----------------
__global__ void k_hist_all(const int* __restrict__ rel_r, const int* __restrict__ tr_c,
                           const int* __restrict__ ig_r) {
    int e = blockIdx.x * blockDim.x + threadIdx.x;
    if (e >= ETOT) return;
    int d;
    if (e < EB1)       d = DB0 + rel_r[e];
    else if (e < EB2)  d = DB1 + rel_r[e];            // rel_r already covers [R,E_UI]
    else if (e < EB3)  d = DB2 + tr_c[e - EB2];
    else if (e < EB4)  d = DB3 + ig_r[e - EB3];
    else               d = DB4 + ig_r[E_II + (e - EB4)];
    atomicAdd(&g_cnt[d], 1);
}

__global__ void k_scan() {
    __shared__ int sh[1024];
    const int DBv[5] = {DB0, DB1, DB2, DB3, DB4};
    const int DSv[5] = {U_NN, U_NN, I_NN, I_NN, I_NN};
    int gsel = blockIdx.x;
    int base = DBv[gsel], size = DSv[gsel];
    int t = threadIdx.x;
    int chunk = (size + 1023) >> 10;
    int lo = t * chunk;
    int hi = lo + chunk; if (hi > size) hi = size;
    if (lo > size) lo = size;
    int s = 0;
    for (int i = lo; i < hi; i++) s += g_cnt[base + i];
    sh[t] = s;
    __syncthreads();
    for (int off = 1; off < 1024; off <<= 1) {
        int v = (t >= off) ? sh[t - off] : 0;
        __syncthreads();
        sh[t] += v;
        __syncthreads();
    }
    int run = (t > 0) ? sh[t - 1] : 0;
    for (int i = lo; i < hi; i++) {
        g_off[base + i] = run;
        g_cur[base + i] = run;
        run += g_cnt[base + i];
    }
    if (gsel == 2) {
        for (int i = lo; i < hi; i++)
            g_invdeg[i] = 1.0f / ((float)g_cnt[DB2 + i] + EPSV);
    }
}

__global__ void k_place_all(const int* __restrict__ rel_r, const int* __restrict__ rel_c,
                            const int* __restrict__ tr_r, const int* __restrict__ tr_c,
                            const int* __restrict__ ig_r, const int* __restrict__ ig_c) {
    int e = blockIdx.x * blockDim.x + threadIdx.x;
    if (e >= ETOT) return;
    int d, src, ebase;
    if (e < EB1)      { d = DB0 + rel_r[e];               src = rel_c[e];               ebase = 0;   }
    else if (e < EB2) { d = DB1 + rel_r[e];               src = rel_c[e];               ebase = 0;   }
    else if (e < EB3) { int j = e - EB2; d = DB2 + tr_c[j]; src = tr_r[j];              ebase = EB2; }
    else if (e < EB4) { int j = e - EB3; d = DB3 + ig_r[j]; src = ig_c[j];              ebase = EB3; }
    else              { int j = e - EB4; d = DB4 + ig_r[E_II + j]; src = ig_c[E_II + j]; ebase = EB4; }
    // rel graphs: cursor already holds absolute position within [0, 2*E_UI)
    int p = atomicAdd(&g_cur[d], 1);
    if (d >= DB1 && d < DB2) ebase = EB1;  // graph 1 edges live at EB1 + off (off is per-graph)
    g_srcA[ebase + p] = src;
}

// ---------------- fused gather (ILP=2) ----------------
__device__ __forceinline__ float4 warp_gather_sum(const int* __restrict__ lst, int deg,
                                                  const float* __restrict__ featBase,
                                                  int lane, int half, int li) {
    float4 accA = make_float4(0.f, 0.f, 0.f, 0.f);
    float4 accB = make_float4(0.f, 0.f, 0.f, 0.f);
    for (int j0 = 0; j0 < deg; j0 += 32) {
        int rem = deg - j0;
        int m = rem < 32 ? rem : 32;
        int myidx = (j0 + lane < deg) ? __ldg(&lst[j0 + lane]) : 0;
        int k = 0;
        for (; k + 4 <= m; k += 4) {
            int iA = __shfl_sync(0xffffffffu, myidx, k + half);
            int iB = __shfl_sync(0xffffffffu, myidx, k + 2 + half);
            float4 vA = *reinterpret_cast<const float4*>(featBase + (long)iA * DT);
            float4 vB = *reinterpret_cast<const float4*>(featBase + (long)iB * DT);
            accA.x += vA.x; accA.y += vA.y; accA.z += vA.z; accA.w += vA.w;
            accB.x += vB.x; accB.y += vB.y; accB.z += vB.z; accB.w += vB.w;
        }
        for (; k < m; k += 2) {
            int kk = k + half;
            int idx = __shfl_sync(0xffffffffu, myidx, kk & 31);
            if (kk < m) {
                float4 v = *reinterpret_cast<const float4*>(featBase + (long)idx * DT);
                accA.x += v.x; accA.y += v.y; accA.z += v.z; accA.w += v.w;
            }
        }
    }
    accA.x += accB.x; accA.y += accB.y; accA.z += accB.z; accA.w += accB.w;
    return accA;
}

__global__ void k_gather_all(int colOff) {
    int w = (blockIdx.x * blockDim.x + threadIdx.x) >> 5;
    if (w >= U_NN + 3 * I_NN) return;
    int lane = threadIdx.x & 31, half = lane >> 4, li = lane & 15;
    float4 r;
    float* dst;
    int row;
    if (w < U_NN) {
        int u = w;
        const float* fb = g_If + colOff + li * 4;
        float4 a0 = warp_gather_sum(g_srcA + g_off[DB0 + u], g_cnt[DB0 + u], fb, lane, half, li);
        float4 a1 = warp_gather_sum(g_srcA + EB1 + g_off[DB1 + u], g_cnt[DB1 + u], fb, lane, half, li);
        float c0 = g_cuser[u * 2 + 0], c1 = g_cuser[u * 2 + 1];
        r.x = c0 * a0.x + c1 * a1.x;
        r.y = c0 * a0.y + c1 * a1.y;
        r.z = c0 * a0.z + c1 * a1.z;
        r.w = c0 * a0.w + c1 * a1.w;
        dst = g_Uagg; row = u;
    } else {
        int v = w - U_NN;
        int gsel = v / I_NN;
        int i = v - gsel * I_NN;
        float4 a; float c;
        if (gsel == 0) {
            a = warp_gather_sum(g_srcA + EB2 + g_off[DB2 + i], g_cnt[DB2 + i],
                                g_Uf + colOff + li * 4, lane, half, li);
            c = g_invdeg[i]; dst = g_Iagg;
        } else if (gsel == 1) {
            a = warp_gather_sum(g_srcA + EB3 + g_off[DB3 + i], g_cnt[DB3 + i],
                                g_If + colOff + li * 4, lane, half, li);
            c = g_invig[0][i]; dst = g_IGagg[0];
        } else {
            a = warp_gather_sum(g_srcA + EB4 + g_off[DB4 + i], g_cnt[DB4 + i],
                                g_If + colOff + li * 4, lane, half, li);
            c = g_invig[1][i]; dst = g_IGagg[1];
        }
        r = make_float4(a.x * c, a.y * c, a.z * c, a.w * c);
        row = i;
    }
    r.x += __shfl_xor_sync(0xffffffffu, r.x, 16);
    r.y += __shfl_xor_sync(0xffffffffu, r.y, 16);
    r.z += __shfl_xor_sync(0xffffffffu, r.z, 16);
    r.w += __shfl_xor_sync(0xffffffffu, r.w, 16);
    if (half == 0)
        *reinterpret_cast<float4*>(&dst[(long)row * DD + li * 4]) = r;
}

// ---------------- fused dense projections (4 gemms, grid.y selects) -------
__global__ void k_gemm_all(const float* __restrict__ W_ui_l,
                           const float* __restrict__ W_ii0_l,
                           const float* __restrict__ W_ii1_l, int colOut) {
    __shared__ __align__(16) float Ws[64 * 64];
    __shared__ __align__(16) float As[64 * 68];
    int sel = blockIdx.y;
    const float* src; float* dst; const float* W; int N;
    if (sel == 0)      { src = g_Uagg;     dst = g_Uf;    W = W_ui_l;  N = U_NN; }
    else if (sel == 1) { src = g_Iagg;     dst = g_If;    W = W_ui_l;  N = I_NN; }
    else if (sel == 2) { src = g_IGagg[0]; dst = g_Sf[0]; W = W_ii0_l; N = I_NN; }
    else               { src = g_IGagg[1]; dst = g_Sf[1]; W = W_ii1_l; N = I_NN; }
    int row0 = blockIdx.x * 64;
    if (row0 >= N) return;
    int tid = threadIdx.x;

    for (int i = tid; i < 4096; i += 256) Ws[i] = W[i];
    for (int i = tid; i < 4096; i += 256) {
        int rr = i >> 6, k = i & 63;
        float v = (row0 + rr < N) ? src[(long)(row0 + rr) * DD + k] : 0.f;
        As[k * 68 + rr] = v;
    }
    __syncthreads();

    int cg = tid & 15, rg = tid >> 4;
    float acc[4][4];
#pragma unroll
    for (int i = 0; i < 4; i++)
#pragma unroll
        for (int j = 0; j < 4; j++) acc[i][j] = 0.f;

#pragma unroll 8
    for (int k = 0; k < 64; k++) {
        float4 a4 = *reinterpret_cast<const float4*>(&As[k * 68 + rg * 4]);
        float4 w4 = *reinterpret_cast<const float4*>(&Ws[k * 64 + cg * 4]);
        float a[4] = {a4.x, a4.y, a4.z, a4.w};
        float w[4] = {w4.x, w4.y, w4.z, w4.w};
#pragma unroll
        for (int i = 0; i < 4; i++)
#pragma unroll
            for (int j = 0; j < 4; j++) acc[i][j] += a[i] * w[j];
    }
#pragma unroll
    for (int i = 0; i < 4; i++) {
        int row = row0 + rg * 4 + i;
        if (row < N) {
            float4 o = make_float4(acc[i][0], acc[i][1], acc[i][2], acc[i][3]);
            *reinterpret_cast<float4*>(&dst[(long)row * DT + colOut + cg * 4]) = o;
        }
    }
}

// ---------------- scoring ----------------
__global__ void k_G(const float* __restrict__ bW, float* out, int lossIdx) {
    __shared__ float Asm[32 * 192];
    __shared__ float Bsm[32 * 192];
    if (blockIdx.x == 0 && blockIdx.y == 0 && blockIdx.z == 0 && threadIdx.x == 0)
        out[lossIdx] = 0.f;
    int r = blockIdx.z;
    const float* W = bW + (long)r * DT * DT;
    int i0 = blockIdx.x * 32, j0 = blockIdx.y * 32;
    for (int t = threadIdx.x; t < 32 * 192; t += 256) {
        Asm[t] = W[(long)(i0 + t / 192) * DT + (t % 192)];
        Bsm[t] = W[(long)(j0 + t / 192) * DT + (t % 192)];
    }
    __syncthreads();
    int tj = threadIdx.x & 15, ti = threadIdx.x >> 4;
    float acc[2][2] = {{0.f, 0.f}, {0.f, 0.f}};
    for (int k = 0; k < 192; k++) {
        float a0 = Asm[(ti * 2 + 0) * 192 + k];
        float a1 = Asm[(ti * 2 + 1) * 192 + k];
        float b0 = Bsm[(tj * 2 + 0) * 192 + k];
        float b1 = Bsm[(tj * 2 + 1) * 192 + k];
        acc[0][0] += a0 * b0; acc[0][1] += a0 * b1;
        acc[1][0] += a1 * b0; acc[1][1] += a1 * b1;
    }
#pragma unroll
    for (int i = 0; i < 2; i++)
#pragma unroll
        for (int j = 0; j < 2; j++)
            g_G[r][(long)(i0 + ti * 2 + i) * DT + (j0 + tj * 2 + j)] = acc[i][j];
}

// block per (b,r), 192 threads: aggregate batched user's rel list, then z = agg @ G
__global__ void k_aggsel_z(const int* __restrict__ users, const int* __restrict__ ubd) {
    __shared__ float as[DT];
    int b = blockIdx.x, r = blockIdx.y, c = threadIdx.x;
    int u = users[b];
    int nb = (r ? DB1 : DB0) + u;
    const int* lst = g_srcA + (r ? EB1 : 0) + g_off[nb];
    int deg = g_cnt[nb];
    const float* S = g_Sf[r];
    float a0 = 0.f, a1 = 0.f;
    int j = 0;
    for (; j + 2 <= deg; j += 2) {
        int iA = __ldg(&lst[j]), iB = __ldg(&lst[j + 1]);
        a0 += S[(long)iA * DT + c];
        a1 += S[(long)iB * DT + c];
    }
    if (j < deg) a0 += S[(long)__ldg(&lst[j]) * DT + c];
    float coeff = 1.0f / ((float)ubd[u * 2 + r] + EPSV);
    as[c] = (a0 + a1) * coeff;
    __syncthreads();
    float acc = 0.f;
    const float* G = g_G[r];
#pragma unroll 4
    for (int k = 0; k < DT; k++) acc += as[k] * G[(long)k * DT + c];
    g_z[r][(long)b * DT + c] = acc;
}

// warp per (b,k); k==0 warp also adds the bu^2*K L2 term
__global__ void k_score(const int* __restrict__ users, const int* __restrict__ items,
                        float* out, int lossIdx) {
    __shared__ float l2blk;
    if (threadIdx.x == 0) l2blk = 0.f;
    __syncthreads();
    int w = (blockIdx.x * blockDim.x + threadIdx.x) >> 5;
    int lane = threadIdx.x & 31;
    if (w < BB * KK) {
        int b = w / KK;
        int kk = w - b * KK;
        int u = users[b];
        int it = items[w];
        float s1 = 0.f, s2a = 0.f, s2b = 0.f, l2i = 0.f, l2u = 0.f;
        for (int c = lane; c < DT; c += 32) {
            float bu = g_Uf[(long)u * DT + c];
            float bi = g_If[(long)it * DT + c];
            s1 += bu * bi;
            l2i += bi * bi;
            if (kk == 0) l2u += bu * bu;
            s2a += g_z[0][(long)b * DT + c] * g_Sf[0][(long)it * DT + c];
            s2b += g_z[1][(long)b * DT + c] * g_Sf[1][(long)it * DT + c];
        }
#pragma unroll
        for (int off = 16; off; off >>= 1) {
            s1  += __shfl_down_sync(0xffffffffu, s1, off);
            s2a += __shfl_down_sync(0xffffffffu, s2a, off);
            s2b += __shfl_down_sync(0xffffffffu, s2b, off);
            l2i += __shfl_down_sync(0xffffffffu, l2i, off);
            if (kk == 0) l2u += __shfl_down_sync(0xffffffffu, l2u, off);
        }
        if (lane == 0) {
            out[w] = 0.5f * s1 + 0.25f * (s2a + s2b);
            atomicAdd(&l2blk, l2i + (kk == 0 ? (float)KK * l2u : 0.f));
        }
    }
    __syncthreads();
    if (threadIdx.x == 0) atomicAdd(out + lossIdx, 1e-4f * l2blk);
}

// ---------------- launch ----------------
extern "C" void kernel_launch(void* const* d_in, const int* in_sizes, int n_in,
                              void* d_out, int out_size) {
    const float* ue    = (const float*)d_in[0];
    const float* ie    = (const float*)d_in[1];
    const float* W_ui  = (const float*)d_in[2];
    const float* W_ii  = (const float*)d_in[3];
    const float* bW    = (const float*)d_in[4];
    const float* mgnn  = (const float*)d_in[5];
    const int* rel_r   = (const int*)d_in[6];
    const int* rel_c   = (const int*)d_in[7];
    const int* tr_r    = (const int*)d_in[8];
    const int* tr_c    = (const int*)d_in[9];
    const int* ig_r    = (const int*)d_in[10];
    const int* ig_c    = (const int*)d_in[11];
    const int* ubd     = (const int*)d_in[12];
    const int* igd     = (const int*)d_in[13];
    const int* users   = (const int*)d_in[14];
    const int* items   = (const int*)d_in[15];
    float* out = (float*)d_out;
    int lossIdx = out_size - 1;

    const int T = 256;
    auto g = [](long n, int t) { return (int)((n + t - 1) / t); };

    // 1-4: init + CSR build
    k_init<<<g((long)(U_NN + I_NN) * DD, T), T>>>(ue, ie, ubd, igd, mgnn);
    k_hist_all<<<g(ETOT, T), T>>>(rel_r, tr_c, ig_r);
    k_scan<<<5, 1024>>>();
    k_place_all<<<g(ETOT, T), T>>>(rel_r, rel_c, tr_r, tr_c, ig_r, ig_c);

    // 5-8: two propagation layers
    for (int l = 0; l < LL; l++) {
        k_gather_all<<<g((long)(U_NN + 3 * I_NN) * 32, T), T>>>(l * DD);
        dim3 gg(g(U_NN, 64), 4);
        k_gemm_all<<<gg, 256>>>(W_ui + (long)l * DD * DD,
                                W_ii + (long)(0 * LL + l) * DD * DD,
                                W_ii + (long)(1 * LL + l) * DD * DD,
                                (l + 1) * DD);
    }

    // 9-11: scoring
    {
        dim3 ggG(6, 6, 2);
        k_G<<<ggG, 256>>>(bW, out, lossIdx);
    }
    {
        dim3 gz(BB, RR);
        k_aggsel_z<<<gz, DT>>>(users, ubd);
    }
    k_score<<<g((long)BB * KK * 32, T), T>>>(users, items, out, lossIdx);
}